// round 16
// baseline (speedup 1.0000x reference)
#include <cuda_runtime.h>
#include <cuda_fp16.h>
#include <cstdint>

// Shapes fixed by the reference
#define N_NODES  100000
#define IN_DIM   128
#define KDIM     256          // 2*IN_DIM
#define HID      64
#define WARPS    11           // warps per block (one block per SM)
#define NTHREADS (WARPS*32)
#define CHUNK_E  32           // edges per warp chunk (M=32)
#define LDAS     132          // A slab row stride in words (128 data + 4 pad)
#define LDW      132          // W1t row stride in words (128 data + 4 pad)
#define GRID     152          // 1 block per SM

#define A_SLAB_WORDS (CHUNK_E*LDAS)
#define SMEM_BYTES ((WARPS*A_SLAB_WORDS + HID*LDW)*4 + (64+64+1)*4)

// fp16 copy of z, gathered via cp.async (25.6 MB static scratch)
__device__ __half zh_g[N_NODES * IN_DIM];

__global__ void convert_z_kernel(const float* __restrict__ z, int n) {
    const int stride = gridDim.x * blockDim.x;
    const int n4 = n >> 2;
    const float4* z4 = reinterpret_cast<const float4*>(z);
    __half2* o2 = reinterpret_cast<__half2*>(zh_g);
    for (int i = blockIdx.x * blockDim.x + threadIdx.x; i < n4; i += stride) {
        float4 v = z4[i];
        o2[i * 2 + 0] = __floats2half2_rn(v.x, v.y);
        o2[i * 2 + 1] = __floats2half2_rn(v.z, v.w);
    }
}

__device__ __forceinline__ void mma_fp16(float* c, const uint32_t* a,
                                         uint32_t b0, uint32_t b1) {
    asm volatile(
        "mma.sync.aligned.m16n8k16.row.col.f32.f16.f16.f32 "
        "{%0,%1,%2,%3}, {%4,%5,%6,%7}, {%8,%9}, {%0,%1,%2,%3};"
        : "+f"(c[0]), "+f"(c[1]), "+f"(c[2]), "+f"(c[3])
        : "r"(a[0]), "r"(a[1]), "r"(a[2]), "r"(a[3]), "r"(b0), "r"(b1));
}

#define LDSM_X4(r0, r1, r2, r3, addr) \
    asm volatile("ldmatrix.sync.aligned.m8n8.x4.shared.b16 {%0,%1,%2,%3}, [%4];" \
        : "=r"(r0), "=r"(r1), "=r"(r2), "=r"(r3) : "r"(addr))

struct GatherCtx {
    const int* e32;
    const long long* e64;
    bool is64;
    const char* zb;
    uint32_t* As32;           // this warp's 32-row slab
    int NE, lane, halfSel, sub;
};

// Issue cp.async gather of one 32-edge chunk into this warp's slab (no waits).
__device__ __forceinline__ void issue_gather(const GatherCtx& c, int chunk) {
    const int ge = chunk * CHUNK_E + c.lane;
    long long sIdx = 0, dIdx = 0;
    if (ge < c.NE) {
        if (c.is64) { sIdx = c.e64[ge]; dIdx = c.e64[(long long)c.NE + ge]; }
        else        { sIdx = (long long)c.e32[ge]; dIdx = (long long)c.e32[c.NE + ge]; }
    }
    #pragma unroll 8
    for (int i = 0; i < 32; i++) {
        const long long s = __shfl_sync(0xffffffffu, sIdx, i);
        const long long d = __shfl_sync(0xffffffffu, dIdx, i);
        const long long row = c.halfSel ? d : s;
        const char* src = c.zb + (row << 8) + c.sub * 16;
        char* dstp = reinterpret_cast<char*>(c.As32)
                   + i * (LDAS * 4) + c.halfSel * 256 + c.sub * 16;
        const uint32_t daddr = (uint32_t)__cvta_generic_to_shared(dstp);
        asm volatile("cp.async.cg.shared.global [%0], [%1], 16;\n"
                     :: "r"(daddr), "l"(src));
    }
    asm volatile("cp.async.commit_group;\n");
}

__global__ __launch_bounds__(NTHREADS, 1)
void mask_predictor_kernel(const void* __restrict__ eidx_raw,
                           const float* __restrict__ W1,
                           const float* __restrict__ b1,
                           const float* __restrict__ W2,
                           const float* __restrict__ b2,
                           float* __restrict__ out,
                           int NE) {
    extern __shared__ unsigned char smem_raw[];
    uint32_t* As32  = reinterpret_cast<uint32_t*>(smem_raw);     // [352][132] words
    uint32_t* W1t32 = As32 + WARPS * A_SLAB_WORDS;               // [64][132] words
    float*    b1s   = reinterpret_cast<float*>(W1t32 + HID * LDW);
    float*    w2s   = b1s + 64;
    float*    b2s   = w2s + 64;
    __half*   W1th  = reinterpret_cast<__half*>(W1t32);          // halves, stride 264

    const int tid  = threadIdx.x;
    const int warp = tid >> 5;
    const int lane = tid & 31;
    const int g    = lane >> 2;   // groupID (0..7)
    const int m    = lane & 3;    // thread-in-group (0..3)

    // ---- Detect edge_index dtype (int64 vs int32) uniformly ----
    const int*       e32 = reinterpret_cast<const int*>(eidx_raw);
    const long long* e64 = reinterpret_cast<const long long*>(eidx_raw);
    bool is64 = true;
    #pragma unroll
    for (int i = 1; i < 32; i += 2) if (e32[i] != 0) is64 = false;

    // ---- Stage W1^T (fp16), b1, W2, b2 (read-only after this barrier) ----
    for (int i = tid; i < KDIM * HID; i += NTHREADS) {
        const int k = i >> 6, n = i & 63;
        W1th[n * (LDW * 2) + k] = __float2half(W1[i]);
    }
    if (tid < 64) { b1s[tid] = b1[tid]; w2s[tid] = W2[tid]; }
    if (tid == 64) { b2s[0] = b2[0]; }
    __syncthreads();

    uint32_t* myAs = As32 + warp * A_SLAB_WORDS;

    // ---- Per-lane ldmatrix base addresses (byte, shared space) ----
    const uint32_t aRow   = (uint32_t)(lane & 15);
    const uint32_t aKoff  = (uint32_t)((lane >> 4) * 16);
    uint32_t aBase[2];
    #pragma unroll
    for (int mt = 0; mt < 2; mt++) {
        aBase[mt] = (uint32_t)__cvta_generic_to_shared(
            reinterpret_cast<char*>(myAs) + (mt * 16 + aRow) * (LDAS * 4)) + aKoff;
    }
    const uint32_t q      = (uint32_t)(lane >> 3);
    const uint32_t bRowIn = ((q >> 1) * 8) + (uint32_t)(lane & 7);
    const uint32_t bKoff  = (q & 1) * 16;
    uint32_t bBase[4];
    #pragma unroll
    for (int p = 0; p < 4; p++) {
        bBase[p] = (uint32_t)__cvta_generic_to_shared(
            reinterpret_cast<char*>(W1t32) + (p * 16 + bRowIn) * (LDW * 4)) + bKoff;
    }

    GatherCtx ctx;
    ctx.e32 = e32; ctx.e64 = e64; ctx.is64 = is64;
    ctx.zb = reinterpret_cast<const char*>(zh_g);
    ctx.As32 = myAs; ctx.NE = NE;
    ctx.lane = lane;
    ctx.halfSel = lane >> 4;
    ctx.sub = lane & 15;

    const int nChunks = (NE + CHUNK_E - 1) / CHUNK_E;
    const int wStride = GRID * WARPS;

    int chunk = blockIdx.x * WARPS + warp;
    if (chunk < nChunks) issue_gather(ctx, chunk);

    for (; chunk < nChunks; chunk += wStride) {
        asm volatile("cp.async.wait_group 0;\n" ::: "memory");
        __syncwarp();   // make lane-written rows visible warp-wide

        // ---- GEMM: 32 edges x 64 cols via ldmatrix + m16n8k16,
        //      with double-buffered fragment registers: LDSM(kt+1) overlaps
        //      the 16 HMMAs of kt (tensor time >> LDS latency). ----
        float acc[2][8][4];
        #pragma unroll
        for (int mt = 0; mt < 2; mt++)
            #pragma unroll
            for (int nt = 0; nt < 8; nt++)
                #pragma unroll
                for (int r = 0; r < 4; r++) acc[mt][nt][r] = 0.f;

        uint32_t a[2][2][4];     // [buf][mtile][frag]
        uint32_t b[2][4][4];     // [buf][pair][frag]

        // Preload kt=0 into buffer 0
        LDSM_X4(a[0][0][0], a[0][0][1], a[0][0][2], a[0][0][3], aBase[0]);
        LDSM_X4(a[0][1][0], a[0][1][1], a[0][1][2], a[0][1][3], aBase[1]);
        LDSM_X4(b[0][0][0], b[0][0][1], b[0][0][2], b[0][0][3], bBase[0]);
        LDSM_X4(b[0][1][0], b[0][1][1], b[0][1][2], b[0][1][3], bBase[1]);
        LDSM_X4(b[0][2][0], b[0][2][1], b[0][2][2], b[0][2][3], bBase[2]);
        LDSM_X4(b[0][3][0], b[0][3][1], b[0][3][2], b[0][3][3], bBase[3]);

        #pragma unroll
        for (int kt = 0; kt < 16; kt++) {
            const int cur = kt & 1;
            const int nb  = cur ^ 1;
            if (kt < 15) {
                const uint32_t kOff = (uint32_t)((kt + 1) * 32);
                LDSM_X4(a[nb][0][0], a[nb][0][1], a[nb][0][2], a[nb][0][3], aBase[0] + kOff);
                LDSM_X4(a[nb][1][0], a[nb][1][1], a[nb][1][2], a[nb][1][3], aBase[1] + kOff);
                LDSM_X4(b[nb][0][0], b[nb][0][1], b[nb][0][2], b[nb][0][3], bBase[0] + kOff);
                LDSM_X4(b[nb][1][0], b[nb][1][1], b[nb][1][2], b[nb][1][3], bBase[1] + kOff);
                LDSM_X4(b[nb][2][0], b[nb][2][1], b[nb][2][2], b[nb][2][3], bBase[2] + kOff);
                LDSM_X4(b[nb][3][0], b[nb][3][1], b[nb][3][2], b[nb][3][3], bBase[3] + kOff);
            }
            #pragma unroll
            for (int p = 0; p < 4; p++) {
                mma_fp16(acc[0][2*p+0], a[cur][0], b[cur][p][0], b[cur][p][1]);
                mma_fp16(acc[1][2*p+0], a[cur][1], b[cur][p][0], b[cur][p][1]);
                mma_fp16(acc[0][2*p+1], a[cur][0], b[cur][p][2], b[cur][p][3]);
                mma_fp16(acc[1][2*p+1], a[cur][1], b[cur][p][2], b[cur][p][3]);
            }
        }

        __syncwarp();   // all lanes done reading As before overwrite

        // ---- Prefetch next chunk's gather; lands during epilogue + peers ----
        const int nxt = chunk + wStride;
        if (nxt < nChunks) issue_gather(ctx, nxt);

        // ---- Epilogue: bias + ReLU + W2 dot + sigmoid ----
        float p4[4] = {0.f, 0.f, 0.f, 0.f};  // rows g, g+8, g+16, g+24
        #pragma unroll
        for (int mt = 0; mt < 2; mt++) {
            #pragma unroll
            for (int nt = 0; nt < 8; nt++) {
                const int c = nt * 8 + 2 * m;
                const float ba = b1s[c], bb = b1s[c + 1];
                const float wa = w2s[c], wb = w2s[c + 1];
                float h;
                h = acc[mt][nt][0] + ba; p4[mt * 2 + 0] += fmaxf(h, 0.f) * wa;
                h = acc[mt][nt][1] + bb; p4[mt * 2 + 0] += fmaxf(h, 0.f) * wb;
                h = acc[mt][nt][2] + ba; p4[mt * 2 + 1] += fmaxf(h, 0.f) * wa;
                h = acc[mt][nt][3] + bb; p4[mt * 2 + 1] += fmaxf(h, 0.f) * wb;
            }
        }
        #pragma unroll
        for (int j = 0; j < 4; j++) {
            p4[j] += __shfl_xor_sync(0xffffffffu, p4[j], 1);
            p4[j] += __shfl_xor_sync(0xffffffffu, p4[j], 2);
        }
        if (m == 0) {
            const float bias2 = b2s[0];
            const int base = chunk * CHUNK_E;
            #pragma unroll
            for (int j = 0; j < 4; j++) {
                const int e = base + (j >> 1) * 16 + (j & 1) * 8 + g;
                if (e < NE)
                    out[e] = 1.f / (1.f + __expf(-(p4[j] + bias2)));
            }
        }
    }
}

extern "C" void kernel_launch(void* const* d_in, const int* in_sizes, int n_in,
                              void* d_out, int out_size) {
    const float* z    = (const float*)d_in[0];
    const void*  eidx = d_in[1];
    const float* W1   = (const float*)d_in[2];
    const float* b1   = (const float*)d_in[3];
    const float* W2   = (const float*)d_in[4];
    const float* b2   = (const float*)d_in[5];
    float*       out  = (float*)d_out;

    const int NE = in_sizes[1] / 2;  // edge_index is (2, E)
    const int nZ = in_sizes[0];      // N_NODES * IN_DIM

    static bool attr_set = false;
    if (!attr_set) {
        cudaFuncSetAttribute(mask_predictor_kernel,
                             cudaFuncAttributeMaxDynamicSharedMemorySize, SMEM_BYTES);
        attr_set = true;
    }

    convert_z_kernel<<<152, 256>>>(z, nZ);
    mask_predictor_kernel<<<GRID, NTHREADS, SMEM_BYTES>>>(eidx, W1, b1, W2, b2, out, NE);
}

// round 17
// speedup vs baseline: 1.1789x; 1.1789x over previous
#include <cuda_runtime.h>
#include <cuda_fp16.h>
#include <cstdint>

// Shapes fixed by the reference
#define IN_DIM   128
#define HID      64
#define NCAT     128            // u(64) || v(64) per node
#define MAXNODES 100000

// Precomputed per-node table: uv[n][0:64] = W1a^T z[n] + b1 (fp16),
//                             uv[n][64:128] = W1b^T z[n] (fp16).  25.6 MB.
__device__ __half uv_g[MAXNODES * NCAT];

// ---------------------------------------------------------------------------
// Node kernel: uv = [z @ W1a + b1 | z @ W1b]  via m16n8k16 fp16 mma
// ---------------------------------------------------------------------------
#define NWARPS_N   8
#define NTHREADS_N 256
#define GRID_N     152
#define ROWB       272          // bytes per staged row: 128 halves + 8 pad halves
#define BT_BYTES   (128*ROWB)
#define SLAB_BYTES (16*ROWB)
#define SMEM_N     (BT_BYTES + NWARPS_N*SLAB_BYTES + 256)

__device__ __forceinline__ void mma_fp16(float* c, const uint32_t* a,
                                         uint32_t b0, uint32_t b1) {
    asm volatile(
        "mma.sync.aligned.m16n8k16.row.col.f32.f16.f16.f32 "
        "{%0,%1,%2,%3}, {%4,%5,%6,%7}, {%8,%9}, {%0,%1,%2,%3};"
        : "+f"(c[0]), "+f"(c[1]), "+f"(c[2]), "+f"(c[3])
        : "r"(a[0]), "r"(a[1]), "r"(a[2]), "r"(a[3]), "r"(b0), "r"(b1));
}

#define LDSM_X4(r0, r1, r2, r3, addr) \
    asm volatile("ldmatrix.sync.aligned.m8n8.x4.shared.b16 {%0,%1,%2,%3}, [%4];" \
        : "=r"(r0), "=r"(r1), "=r"(r2), "=r"(r3) : "r"(addr))

__global__ __launch_bounds__(NTHREADS_N, 1)
void node_kernel(const float* __restrict__ z,
                 const float* __restrict__ W1,
                 const float* __restrict__ b1,
                 int nNodes) {
    extern __shared__ unsigned char sm[];
    __half* Bt  = reinterpret_cast<__half*>(sm);             // [128 n][136 halves]
    unsigned char* slabs = sm + BT_BYTES;
    float*  b1s = reinterpret_cast<float*>(sm + BT_BYTES + NWARPS_N * SLAB_BYTES);

    const int tid  = threadIdx.x;
    const int warp = tid >> 5;
    const int lane = tid & 31;
    const int g    = lane >> 2;
    const int m    = lane & 3;

    // Fill B^T: col n of [W1a|W1b], k = 0..127. W1 is row-major (256,64).
    for (int i = tid; i < 128 * 128; i += NTHREADS_N) {
        const int n = i & 127, k = i >> 7;
        const float v = (n < 64) ? W1[k * 64 + n] : W1[(128 + k) * 64 + (n - 64)];
        Bt[n * 136 + k] = __float2half(v);
    }
    if (tid < 64) b1s[tid] = b1[tid];
    __syncthreads();

    __half* slab = reinterpret_cast<__half*>(slabs + warp * SLAB_BYTES);

    const uint32_t aBase = (uint32_t)__cvta_generic_to_shared(
        reinterpret_cast<char*>(slab) + (lane & 15) * ROWB)
        + (uint32_t)((lane >> 4) * 16);
    const uint32_t q      = (uint32_t)(lane >> 3);
    const uint32_t bRowIn = ((q >> 1) * 8) + (uint32_t)(lane & 7);
    const uint32_t bKoff  = (q & 1) * 16;
    uint32_t bBase[8];
    #pragma unroll
    for (int p = 0; p < 8; p++) {
        bBase[p] = (uint32_t)__cvta_generic_to_shared(
            reinterpret_cast<char*>(Bt) + (p * 16 + bRowIn) * ROWB) + bKoff;
    }

    const int nChunks = (nNodes + 15) / 16;
    const float4* z4 = reinterpret_cast<const float4*>(z);

    for (int chunk = blockIdx.x * NWARPS_N + warp; chunk < nChunks;
         chunk += GRID_N * NWARPS_N) {
        const int base = chunk * 16;

        // Stage A: 16 node rows fp32 -> fp16 (8B stores, 272B row stride)
        #pragma unroll 4
        for (int idx = lane; idx < 16 * 32; idx += 32) {
            const int row = idx >> 5, c4 = idx & 31;
            const int node = base + row;
            float4 v = make_float4(0.f, 0.f, 0.f, 0.f);
            if (node < nNodes) v = z4[node * 32 + c4];
            __half2 h0 = __floats2half2_rn(v.x, v.y);
            __half2 h1 = __floats2half2_rn(v.z, v.w);
            uint2 hh;
            hh.x = *reinterpret_cast<uint32_t*>(&h0);
            hh.y = *reinterpret_cast<uint32_t*>(&h1);
            *reinterpret_cast<uint2*>(
                reinterpret_cast<char*>(slab) + row * ROWB + c4 * 8) = hh;
        }
        __syncwarp();

        float acc[16][4];
        #pragma unroll
        for (int nt = 0; nt < 16; nt++)
            #pragma unroll
            for (int r = 0; r < 4; r++) acc[nt][r] = 0.f;

        #pragma unroll
        for (int kt = 0; kt < 8; kt++) {
            const uint32_t kOff = (uint32_t)(kt * 32);
            uint32_t a[4];
            LDSM_X4(a[0], a[1], a[2], a[3], aBase + kOff);
            #pragma unroll
            for (int p = 0; p < 8; p++) {
                uint32_t b0, b1r, b2r, b3;
                LDSM_X4(b0, b1r, b2r, b3, bBase[p] + kOff);
                mma_fp16(acc[2 * p + 0], a, b0, b1r);
                mma_fp16(acc[2 * p + 1], a, b2r, b3);
            }
        }
        __syncwarp();   // slab reuse next chunk

        // Epilogue: +b1 on u-half, fp16 pack, store to uv table
        const int node0 = base + g;
        const int node1 = base + g + 8;
        #pragma unroll
        for (int nt = 0; nt < 16; nt++) {
            const int col = nt * 8 + 2 * m;
            float f0 = acc[nt][0], f1 = acc[nt][1];
            float f2 = acc[nt][2], f3 = acc[nt][3];
            if (nt < 8) {
                const float ba = b1s[col], bb = b1s[col + 1];
                f0 += ba; f1 += bb; f2 += ba; f3 += bb;
            }
            if (node0 < nNodes)
                *reinterpret_cast<__half2*>(uv_g + node0 * NCAT + col) =
                    __floats2half2_rn(f0, f1);
            if (node1 < nNodes)
                *reinterpret_cast<__half2*>(uv_g + node1 * NCAT + col) =
                    __floats2half2_rn(f2, f3);
        }
    }
}

// ---------------------------------------------------------------------------
// Edge kernel: out[e] = sigmoid( W2 . relu(u[src] + v[dst]) + b2 )
// 8 lanes per edge, 4 edges per warp-iter; pure gather + FFMA.
// ---------------------------------------------------------------------------
#define NTHREADS_E 256
#define GRID_E     304

__global__ __launch_bounds__(NTHREADS_E)
void edge_kernel(const void* __restrict__ eidx_raw,
                 const float* __restrict__ W2,
                 const float* __restrict__ b2,
                 float* __restrict__ out,
                 int NE) {
    const int tid  = threadIdx.x;
    const int lane = tid & 31;
    const int j    = lane & 7;    // sub-lane within edge (16B of u / v)
    const int slot = lane >> 3;   // edge slot 0..3

    // Detect edge_index dtype (int64 vs int32) uniformly
    const int*       e32 = reinterpret_cast<const int*>(eidx_raw);
    const long long* e64 = reinterpret_cast<const long long*>(eidx_raw);
    bool is64 = true;
    #pragma unroll
    for (int i = 1; i < 32; i += 2) if (e32[i] != 0) is64 = false;

    float w2f[8];
    #pragma unroll
    for (int t = 0; t < 8; t++) w2f[t] = W2[j * 8 + t];
    const float b2v = b2[0];

    const char* uvb = reinterpret_cast<const char*>(uv_g);
    const __half2 zero2 = __float2half2_rn(0.f);

    const int warpGlobal = blockIdx.x * (NTHREADS_E / 32) + (tid >> 5);
    const int stride = GRID_E * (NTHREADS_E / 32) * 4;

    for (int e0 = warpGlobal * 4; e0 < NE; e0 += stride) {
        const int ge = e0 + slot;
        const bool ok = (ge < NE);
        long long s = 0, d = 0;
        if (ok) {
            if (is64) { s = e64[ge]; d = e64[(long long)NE + ge]; }
            else      { s = (long long)e32[ge]; d = (long long)e32[NE + ge]; }
        }
        const uint4 uu = *reinterpret_cast<const uint4*>(uvb + (s << 8) + j * 16);
        const uint4 vv = *reinterpret_cast<const uint4*>(uvb + (d << 8) + 128 + j * 16);
        const __half2* uh = reinterpret_cast<const __half2*>(&uu);
        const __half2* vh = reinterpret_cast<const __half2*>(&vv);

        float p = 0.f;
        #pragma unroll
        for (int t = 0; t < 4; t++) {
            __half2 h = __hadd2(uh[t], vh[t]);
            h = __hmax2(h, zero2);
            p = fmaf(__low2float(h),  w2f[2 * t],     p);
            p = fmaf(__high2float(h), w2f[2 * t + 1], p);
        }
        p += __shfl_xor_sync(0xffffffffu, p, 1);
        p += __shfl_xor_sync(0xffffffffu, p, 2);
        p += __shfl_xor_sync(0xffffffffu, p, 4);

        if (j == 0 && ok)
            out[ge] = 1.f / (1.f + __expf(-(p + b2v)));
    }
}

extern "C" void kernel_launch(void* const* d_in, const int* in_sizes, int n_in,
                              void* d_out, int out_size) {
    const float* z    = (const float*)d_in[0];
    const void*  eidx = d_in[1];
    const float* W1   = (const float*)d_in[2];
    const float* b1   = (const float*)d_in[3];
    const float* W2   = (const float*)d_in[4];
    const float* b2   = (const float*)d_in[5];
    float*       out  = (float*)d_out;

    const int NE     = in_sizes[1] / 2;       // edge_index is (2, E)
    const int nNodes = in_sizes[0] / IN_DIM;  // z is (N, 128)

    static bool attr_set = false;
    if (!attr_set) {
        cudaFuncSetAttribute(node_kernel,
                             cudaFuncAttributeMaxDynamicSharedMemorySize, SMEM_N);
        attr_set = true;
    }

    node_kernel<<<GRID_N, NTHREADS_N, SMEM_N>>>(z, W1, b1, nNodes);
    edge_kernel<<<GRID_E, NTHREADS_E>>>(eidx, W2, b2, out, NE);
}